// round 3
// baseline (speedup 1.0000x reference)
#include <cuda_runtime.h>
#include <cstdint>

#define NE 256
#define NC 48
#define NB 64
#define NT 1024
#define ROWS 128
#define KT   32
#define PADW 36          // 36 % 32 == 4 -> conflict-free strided LDS
#define NTILES 512       // (NB*NT)/ROWS
#define CRF_BLOCKS 64

// dynamic smem layout (floats):
//   [0 .. 6336)      buffer 0: fcw(48*36=1728) + emb(128*36=4608)
//   [6336 .. 12672)  buffer 1
//   [12672 ..)       x_s (128 ints)
// CRF path reuses [0..192) for a_sh[2][64] + red[64]
#define BUF_FLOATS 6336
#define SMEM_BYTES (12672 * 4 + ROWS * 4)

static __device__ float g_partial[NB];
static __device__ int   g_flags[NTILES];

// ---------- packed f32x2 helpers ----------
__device__ __forceinline__ unsigned long long ffma2(unsigned long long a, unsigned long long b,
                                                    unsigned long long c) {
    unsigned long long d;
    asm("fma.rn.f32x2 %0, %1, %2, %3;" : "=l"(d) : "l"(a), "l"(b), "l"(c));
    return d;
}
__device__ __forceinline__ unsigned long long fadd2(unsigned long long a, unsigned long long b) {
    unsigned long long d;
    asm("add.rn.f32x2 %0, %1, %2;" : "=l"(d) : "l"(a), "l"(b));
    return d;
}
__device__ __forceinline__ float2 unpack2(unsigned long long a) {
    float2 f;
    asm("mov.b64 {%0, %1}, %2;" : "=f"(f.x), "=f"(f.y) : "l"(a));
    return f;
}
__device__ __forceinline__ unsigned long long pack2(float x, float y) {
    unsigned long long d;
    asm("mov.b64 %0, {%1, %2};" : "=l"(d) : "f"(x), "f"(y));
    return d;
}
__device__ __forceinline__ float frcp_fast(float x) {
    float r; asm("rcp.approx.f32 %0, %1;" : "=f"(r) : "f"(x)); return r;
}
__device__ __forceinline__ uint32_t smem_u32(const void* p) {
    uint32_t a;
    asm("{ .reg .u64 t; cvta.to.shared.u64 t, %1; cvt.u32.u64 %0, t; }" : "=r"(a) : "l"(p));
    return a;
}
__device__ __forceinline__ void ldgsts16(uint32_t dst, const void* src) {
    asm volatile("cp.async.cg.shared.global [%0], [%1], 16;" :: "r"(dst), "l"(src));
}

// ============================================================================
// Fused kernel.
//  blocks [0, 64):    CRF forward scan, one chain per block (64 live threads)
//  blocks [64, 576):  GEMM tiles, chunk-major order: tileIdx = blockIdx-64,
//                     chain b = tileIdx % 64, time-chunk c = tileIdx / 64,
//                     rows = b*1024 + c*128. Flag id = b*8 + c.
// GEMM -> flag (release); CRF spins on flag (acquire) before touching a chunk.
// ============================================================================
__global__ __launch_bounds__(256, 3) void fused_kernel(
    const int* __restrict__ x, const int* __restrict__ labels,
    const float* __restrict__ emb, const float* __restrict__ fcw,
    const float* __restrict__ fcb, const float* __restrict__ start_trans,
    const float* __restrict__ end_trans, const float* __restrict__ trans,
    float* __restrict__ out)
{
    extern __shared__ float sm[];
    const int tid = threadIdx.x;

    if (blockIdx.x >= CRF_BLOCKS) {
        // ==================== GEMM path ====================
        const int tileIdx  = blockIdx.x - CRF_BLOCKS;
        const int chainB   = tileIdx & 63;
        const int chunkC   = tileIdx >> 6;
        const int rowBase  = chainB * NT + chunkC * ROWS;
        const int flagId   = chainB * 8 + chunkC;

        int* x_s = (int*)(sm + 2 * BUF_FLOATS);
        if (tid < ROWS) x_s[tid] = x[rowBase + tid];
        __syncthreads();

        const uint32_t smbase = smem_u32(sm);

        // async-load one K-tile into buffer `buf`
        #define LOAD_TILE(KIDX, BUF)                                               \
        {                                                                          \
            const int k0 = (KIDX) * KT;                                            \
            const uint32_t fb  = smbase + (BUF) * BUF_FLOATS * 4;                  \
            const uint32_t ebs = fb + 1728 * 4;                                    \
            for (int i = tid; i < 1408; i += 256) {                                \
                if (i < 384) {                                                     \
                    int r = i >> 3, k4 = i & 7;                                    \
                    ldgsts16(fb + (r * PADW + 4 * k4) * 4,                         \
                             fcw + r * NE + k0 + 4 * k4);                          \
                } else {                                                           \
                    int j = i - 384; int r = j >> 3, k4 = j & 7;                   \
                    ldgsts16(ebs + (r * PADW + 4 * k4) * 4,                        \
                             emb + (size_t)x_s[r] * NE + k0 + 4 * k4);             \
                }                                                                  \
            }                                                                      \
            asm volatile("cp.async.commit_group;");                                \
        }

        LOAD_TILE(0, 0);

        const int tx = tid & 7;   // col group
        const int ty = tid >> 3;  // row group 0..31

        unsigned long long acc[4][6];
        #pragma unroll
        for (int m = 0; m < 4; m++)
            #pragma unroll
            for (int n = 0; n < 6; n++) acc[m][n] = 0ull;

        for (int kt = 0; kt < 8; kt++) {
            asm volatile("cp.async.wait_group 0;");
            __syncthreads();
            if (kt < 7) LOAD_TILE(kt + 1, (kt + 1) & 1);

            const float* fcw_s = sm + (kt & 1) * BUF_FLOATS;
            const float* emb_s = fcw_s + 1728;

            #pragma unroll 4
            for (int k2 = 0; k2 < KT / 2; k2++) {
                unsigned long long a2[4], w2[6];
                #pragma unroll
                for (int m = 0; m < 4; m++)
                    a2[m] = *(const unsigned long long*)&emb_s[(ty + 32 * m) * PADW + 2 * k2];
                #pragma unroll
                for (int n = 0; n < 6; n++)
                    w2[n] = *(const unsigned long long*)&fcw_s[(tx + 8 * n) * PADW + 2 * k2];
                #pragma unroll
                for (int m = 0; m < 4; m++)
                    #pragma unroll
                    for (int n = 0; n < 6; n++)
                        acc[m][n] = ffma2(a2[m], w2[n], acc[m][n]);
            }
            __syncthreads();
        }
        #undef LOAD_TILE

        #pragma unroll
        for (int m = 0; m < 4; m++) {
            int r = rowBase + ty + 32 * m;
            #pragma unroll
            for (int n = 0; n < 6; n++) {
                int c = tx + 8 * n;
                float2 p = unpack2(acc[m][n]);
                out[(size_t)r * NC + c] = p.x + p.y + __ldg(&fcb[c]);
            }
        }
        // release: make logits visible, then set flag
        __threadfence();
        __syncthreads();
        if (tid == 0) atomicExch(&g_flags[flagId], 1);
        return;
    }

    // ==================== CRF path ====================
    if (tid >= 64) return;

    float (*a_sh)[64] = (float(*)[64])sm;   // [2][64]
    float* red = sm + 128;

    const int b   = blockIdx.x;
    const float* lg  = out    + (size_t)b * NT * NC;
    const int*   lab = labels + b * NT;
    const int flagBase = b * 8;

    // acquire-wait for chunk `need`
    #define WAIT_CHUNK(NEED)                                                   \
    {                                                                          \
        if (tid == 0) {                                                        \
            volatile int* f = &g_flags[flagBase + (NEED)];                     \
            while (*f == 0) __nanosleep(64);                                   \
            __threadfence();                                                   \
        }                                                                      \
        __syncthreads();                                                       \
    }

    const int cc = (tid < NC) ? tid : (NC - 1);

    unsigned long long Ec2[24];
    #pragma unroll
    for (int j = 0; j < 24; j++) {
        float e0 = __expf(trans[(2 * j)     * NC + cc]) * 0.015625f;  // /64
        float e1 = __expf(trans[(2 * j + 1) * NC + cc]) * 0.015625f;
        Ec2[j] = pack2(e0, e1);
    }

    WAIT_CHUNK(0);
    float a_cur = __expf(start_trans[cc] + lg[cc]);
    a_sh[0][tid] = a_cur;

    float logscale = 0.f;
    float eb[4];
    #pragma unroll
    for (int jj = 0; jj < 4; jj++) eb[jj] = lg[(1 + jj) * NC + cc];
    __syncthreads();

    int p = 0;
    int ready = 0;

    #define CRF_STEP(T, EMIS)                                                  \
    {                                                                          \
        float ex = __expf(EMIS);                                               \
        float r  = a_sh[p][0];                                                 \
        unsigned long long s0 = 0ull, s1 = 0ull, s2 = 0ull, s3 = 0ull;         \
        _Pragma("unroll")                                                      \
        for (int j = 0; j < 12; j += 2) {                                      \
            ulonglong2 u = *(const ulonglong2*)&a_sh[p][4 * j];                \
            ulonglong2 v = *(const ulonglong2*)&a_sh[p][4 * j + 4];            \
            s0 = ffma2(u.x, Ec2[2 * j],     s0);                               \
            s1 = ffma2(u.y, Ec2[2 * j + 1], s1);                               \
            s2 = ffma2(v.x, Ec2[2 * j + 2], s2);                               \
            s3 = ffma2(v.y, Ec2[2 * j + 3], s3);                               \
        }                                                                      \
        float2 sp = unpack2(fadd2(fadd2(s0, s2), fadd2(s1, s3)));              \
        float s = sp.x + sp.y;                                                 \
        bool rn = ((T) & 127) == 0;                                            \
        float sel = rn ? frcp_fast(r) : 1.0f;                                  \
        logscale += rn ? __logf(r) : 0.0f;                                     \
        float anew = s * ex * sel;                                             \
        a_sh[p ^ 1][tid] = anew;                                               \
        a_cur = anew;                                                          \
        __syncthreads();                                                       \
        p ^= 1;                                                                \
    }

    for (int tb = 1; tb + 3 < NT; tb += 4) {
        int need = (tb + 7) >> 7;
        need = (need > 7) ? 7 : need;
        if (need > ready) { WAIT_CHUNK(need); ready = need; }

        float en[4];
        #pragma unroll
        for (int jj = 0; jj < 4; jj++) {
            int tt = tb + 4 + jj;
            tt = (tt < NT) ? tt : (NT - 1);
            en[jj] = lg[tt * NC + cc];
        }
        CRF_STEP(tb + 0, eb[0]);
        CRF_STEP(tb + 1, eb[1]);
        CRF_STEP(tb + 2, eb[2]);
        CRF_STEP(tb + 3, eb[3]);
        eb[0] = en[0]; eb[1] = en[1]; eb[2] = en[2]; eb[3] = en[3];
    }
    CRF_STEP(NT - 3, eb[0]);
    CRF_STEP(NT - 2, eb[1]);
    CRF_STEP(NT - 1, eb[2]);
    #undef CRF_STEP
    #undef WAIT_CHUNK

    // ---- logZ partial ----
    if (tid < NC) red[tid] = a_cur * __expf(end_trans[tid]);
    __syncthreads();
    float logz_part = 0.f;
    if (tid == 0) {
        float s = 0.f;
        #pragma unroll
        for (int i = 0; i < NC; i++) s += red[i];
        logz_part = __logf(s) + logscale + 4254.5374f;   // + 1023*ln(64)
    }
    __syncthreads();

    // ---- numerator (all chunks ready now), fixed-order reduce ----
    float acc = 0.f;
    for (int t = tid; t < NT; t += 64) {
        int lt = lab[t];
        acc += lg[t * NC + lt];
        if (t + 1 < NT) acc += trans[lt * NC + lab[t + 1]];
    }
    if (tid == 0)  acc += start_trans[lab[0]];
    if (tid == 63) acc += end_trans[lab[NT - 1]];
    red[tid] = acc;
    __syncthreads();
    if (tid == 0) {
        float num = 0.f;
        #pragma unroll
        for (int i = 0; i < 64; i++) num += red[i];
        g_partial[b] = num - logz_part;
    }
}

// ============================================================================
// final deterministic reduce -> d_out[out_size-1] = -llh
// ============================================================================
__global__ void finish_kernel(float* __restrict__ out, int out_size)
{
    if (threadIdx.x == 0 && blockIdx.x == 0) {
        float s = 0.f;
        #pragma unroll
        for (int i = 0; i < NB; i++) s += g_partial[i];
        out[out_size - 1] = -s;
    }
}

extern "C" void kernel_launch(void* const* d_in, const int* in_sizes, int n_in,
                              void* d_out, int out_size)
{
    const int*   x    = (const int*)  d_in[0];
    const int*   lab  = (const int*)  d_in[1];
    const float* emb  = (const float*)d_in[2];
    const float* fcw  = (const float*)d_in[3];
    const float* fcb  = (const float*)d_in[4];
    const float* st   = (const float*)d_in[5];
    const float* et   = (const float*)d_in[6];
    const float* tr   = (const float*)d_in[7];
    float* out = (float*)d_out;

    void* flagsAddr = nullptr;
    cudaGetSymbolAddress(&flagsAddr, g_flags);
    cudaMemsetAsync(flagsAddr, 0, NTILES * sizeof(int));

    cudaFuncSetAttribute(fused_kernel, cudaFuncAttributeMaxDynamicSharedMemorySize, SMEM_BYTES);
    fused_kernel<<<CRF_BLOCKS + NTILES, 256, SMEM_BYTES>>>(x, lab, emb, fcw, fcb, st, et, tr, out);
    finish_kernel<<<1, 32>>>(out, out_size);
}

// round 5
// speedup vs baseline: 1.3320x; 1.3320x over previous
#include <cuda_runtime.h>
#include <cstdint>

#define NE 256
#define NC 48
#define NB 64
#define NT 1024
#define ROWS 128
#define KT   32
#define PADW 36          // 36 % 32 == 4 -> conflict-free strided LDS; mult of 4 for STS.128
#define NTILES 512       // (NB*NT)/ROWS
#define BUF_FLOATS 6336  // fcw 48*36 + emb 128*36
#define GEMM_SMEM (2 * BUF_FLOATS * 4 + ROWS * 4)

static __device__ float g_exp[NB * NT * NC];   // exp(logits) scratch (12.6 MB)
static __device__ float g_partial[NB];
static __device__ int   g_done;                // zero-init; self-resets each run

// ---------- packed f32x2 helpers ----------
__device__ __forceinline__ unsigned long long ffma2(unsigned long long a, unsigned long long b,
                                                    unsigned long long c) {
    unsigned long long d;
    asm("fma.rn.f32x2 %0, %1, %2, %3;" : "=l"(d) : "l"(a), "l"(b), "l"(c));
    return d;
}
__device__ __forceinline__ unsigned long long fadd2(unsigned long long a, unsigned long long b) {
    unsigned long long d;
    asm("add.rn.f32x2 %0, %1, %2;" : "=l"(d) : "l"(a), "l"(b));
    return d;
}
__device__ __forceinline__ float2 unpack2(unsigned long long a) {
    float2 f;
    asm("mov.b64 {%0, %1}, %2;" : "=f"(f.x), "=f"(f.y) : "l"(a));
    return f;
}
__device__ __forceinline__ unsigned long long pack2(float x, float y) {
    unsigned long long d;
    asm("mov.b64 %0, {%1, %2};" : "=l"(d) : "f"(x), "f"(y));
    return d;
}
__device__ __forceinline__ float frcp_fast(float x) {
    float r; asm("rcp.approx.f32 %0, %1;" : "=f"(r) : "f"(x)); return r;
}
__device__ __forceinline__ uint32_t smem_u32(const void* p) {
    uint32_t a;
    asm("{ .reg .u64 t; cvta.to.shared.u64 t, %1; cvt.u32.u64 %0, t; }" : "=r"(a) : "l"(p));
    return a;
}
__device__ __forceinline__ void ldgsts16(uint32_t dst, const void* src) {
    asm volatile("cp.async.cg.shared.global [%0], [%1], 16;" :: "r"(dst), "l"(src));
}

// ============================================================================
// Kernel 1: logits = gather(emb)[65536x256] @ fc_w^T[48x256] + fc_b
// 256 threads, 3 blocks/SM, thread tile 4x6, K split into 8 tiles of 32,
// cp.async double-buffered. Also writes exp(logits) into g_exp.
// ============================================================================
__global__ __launch_bounds__(256, 3) void gemm_kernel(
    const int* __restrict__ x, const float* __restrict__ emb,
    const float* __restrict__ fcw, const float* __restrict__ fcb,
    float* __restrict__ out)
{
    extern __shared__ float sm[];
    int* x_s = (int*)(sm + 2 * BUF_FLOATS);

    const int tid = threadIdx.x;
    const int rowBase = blockIdx.x * ROWS;
    if (tid < ROWS) x_s[tid] = x[rowBase + tid];
    __syncthreads();

    const uint32_t smbase = smem_u32(sm);

    #define LOAD_TILE(KIDX, BUF)                                               \
    {                                                                          \
        const int k0 = (KIDX) * KT;                                            \
        const uint32_t fb  = smbase + (BUF) * BUF_FLOATS * 4;                  \
        const uint32_t ebs = fb + 1728 * 4;                                    \
        for (int i = tid; i < 384; i += 256) {                                 \
            int r = i >> 3, k4 = i & 7;                                        \
            ldgsts16(fb + (r * PADW + 4 * k4) * 4, fcw + r * NE + k0 + 4 * k4);\
        }                                                                      \
        for (int i = tid; i < 1024; i += 256) {                                \
            int r = i >> 3, k4 = i & 7;                                        \
            ldgsts16(ebs + (r * PADW + 4 * k4) * 4,                            \
                     emb + (size_t)x_s[r] * NE + k0 + 4 * k4);                 \
        }                                                                      \
        asm volatile("cp.async.commit_group;");                                \
    }

    LOAD_TILE(0, 0);

    const int tx = tid & 7;   // col group
    const int ty = tid >> 3;  // row group 0..31

    unsigned long long acc[4][6];
    #pragma unroll
    for (int m = 0; m < 4; m++)
        #pragma unroll
        for (int n = 0; n < 6; n++) acc[m][n] = 0ull;

    for (int kt = 0; kt < 8; kt++) {
        if (kt < 7) {
            LOAD_TILE(kt + 1, (kt + 1) & 1);                 // prefetch next
            asm volatile("cp.async.wait_group %0;" :: "n"(1)); // tile kt ready
        } else {
            asm volatile("cp.async.wait_group %0;" :: "n"(0)); // ALL done (fix)
        }
        __syncthreads();

        const float* fcw_s = sm + (kt & 1) * BUF_FLOATS;
        const float* emb_s = fcw_s + 1728;

        #pragma unroll 4
        for (int k2 = 0; k2 < KT / 2; k2++) {
            unsigned long long a2[4], w2[6];
            #pragma unroll
            for (int m = 0; m < 4; m++)
                a2[m] = *(const unsigned long long*)&emb_s[(ty + 32 * m) * PADW + 2 * k2];
            #pragma unroll
            for (int n = 0; n < 6; n++)
                w2[n] = *(const unsigned long long*)&fcw_s[(tx + 8 * n) * PADW + 2 * k2];
            #pragma unroll
            for (int m = 0; m < 4; m++)
                #pragma unroll
                for (int n = 0; n < 6; n++)
                    acc[m][n] = ffma2(a2[m], w2[n], acc[m][n]);
        }
        __syncthreads();
    }
    #undef LOAD_TILE

    #pragma unroll
    for (int m = 0; m < 4; m++) {
        int r = rowBase + ty + 32 * m;
        #pragma unroll
        for (int n = 0; n < 6; n++) {
            int c = tx + 8 * n;
            float2 p = unpack2(acc[m][n]);
            float v = p.x + p.y + __ldg(&fcb[c]);
            out[(size_t)r * NC + c]   = v;
            g_exp[(size_t)r * NC + c] = __expf(v);
        }
    }
}

// ============================================================================
// Kernel 2: CRF forward scan. One block/chain, 64 threads, branch-free steps.
// Inner step: LDS alpha -> 24 FFMA2 (4 chains) -> tree -> *exp(emis) -> STS
// -> bar. exp(emis) precomputed in g_exp. Renorm only at chunk boundaries.
// Last block to finish does the final 64-way reduce (no finish kernel).
// ============================================================================
__global__ __launch_bounds__(64) void crf_kernel(
    const float* __restrict__ logits,
    const int* __restrict__ labels,
    const float* __restrict__ start_trans,
    const float* __restrict__ end_trans,
    const float* __restrict__ trans,
    float* __restrict__ out, int out_size)
{
    __shared__ __align__(16) float a_sh[2][64];
    __shared__ float red[64];

    const int b   = blockIdx.x;
    const int tid = threadIdx.x;
    const float* lg  = logits + (size_t)b * NT * NC;
    const float* ge  = g_exp  + (size_t)b * NT * NC;
    const int*   lab = labels + b * NT;

    // ---- numerator (parallel over t, fixed-order reduce) ----
    float acc = 0.f;
    for (int t = tid; t < NT; t += 64) {
        int lt = lab[t];
        acc += lg[t * NC + lt];
        if (t + 1 < NT) acc += trans[lt * NC + lab[t + 1]];
    }
    if (tid == 0)  acc += start_trans[lab[0]];
    if (tid == 63) acc += end_trans[lab[NT - 1]];
    red[tid] = acc;

    // ---- branch-free setup ----
    const int cc = (tid < NC) ? tid : (NC - 1);

    unsigned long long Ec2[24];
    #pragma unroll
    for (int j = 0; j < 24; j++) {
        float e0 = __expf(trans[(2 * j)     * NC + cc]) * 0.015625f;  // /64
        float e1 = __expf(trans[(2 * j + 1) * NC + cc]) * 0.015625f;
        Ec2[j] = pack2(e0, e1);
    }
    float a_cur = __expf(start_trans[cc]) * ge[cc];   // exp(start + logits[:,0])
    a_sh[0][tid] = a_cur;

    float logscale = 0.f;
    float eb[4];
    #pragma unroll
    for (int jj = 0; jj < 4; jj++) eb[jj] = ge[(1 + jj) * NC + cc];
    __syncthreads();

    int p = 0;

    #define CRF_STEP(EXL)                                                      \
    {                                                                          \
        unsigned long long s0 = 0ull, s1 = 0ull, s2 = 0ull, s3 = 0ull;         \
        _Pragma("unroll")                                                      \
        for (int j = 0; j < 12; j += 2) {                                      \
            ulonglong2 u = *(const ulonglong2*)&a_sh[p][4 * j];                \
            ulonglong2 v = *(const ulonglong2*)&a_sh[p][4 * j + 4];            \
            s0 = ffma2(u.x, Ec2[2 * j],     s0);                               \
            s1 = ffma2(u.y, Ec2[2 * j + 1], s1);                               \
            s2 = ffma2(v.x, Ec2[2 * j + 2], s2);                               \
            s3 = ffma2(v.y, Ec2[2 * j + 3], s3);                               \
        }                                                                      \
        float2 sp = unpack2(fadd2(fadd2(s0, s2), fadd2(s1, s3)));              \
        float anew = (sp.x + sp.y) * (EXL);                                    \
        a_sh[p ^ 1][tid] = anew;                                               \
        a_cur = anew;                                                          \
        __syncthreads();                                                       \
        p ^= 1;                                                                \
    }

    // 255 groups of 4 steps (t = 1..1020) in 8 chunks; renorm between chunks
    int g = 0;
    for (int ch = 0; ch < 8; ch++) {
        const int glim = (ch < 7) ? 32 : 31;
        for (int gi = 0; gi < glim; gi++, g++) {
            const int tnext = 4 * g + 5;
            float en[4];
            #pragma unroll
            for (int jj = 0; jj < 4; jj++) {
                int tt = tnext + jj;
                tt = (tt < NT) ? tt : (NT - 1);
                en[jj] = ge[tt * NC + cc];
            }
            CRF_STEP(eb[0]);
            CRF_STEP(eb[1]);
            CRF_STEP(eb[2]);
            CRF_STEP(eb[3]);
            eb[0] = en[0]; eb[1] = en[1]; eb[2] = en[2]; eb[3] = en[3];
        }
        if (ch < 7) {
            float r = a_sh[p][0];       // all threads read slot 0
            __syncthreads();            // ... before it is overwritten below
            a_cur *= frcp_fast(r);
            a_sh[p][tid] = a_cur;
            logscale += __logf(r);      // identical in every thread
            __syncthreads();
        }
    }
    // epilogue: t = 1021, 1022, 1023
    CRF_STEP(eb[0]);
    CRF_STEP(eb[1]);
    CRF_STEP(eb[2]);
    #undef CRF_STEP

    // ---- logZ + per-chain partial; last block reduces everything ----
    float numer = 0.f;
    if (tid == 0) {
        #pragma unroll
        for (int i = 0; i < 64; i++) numer += red[i];
    }
    __syncthreads();
    if (tid < NC) red[tid] = a_cur * __expf(end_trans[tid]);
    __syncthreads();
    if (tid == 0) {
        float s = 0.f;
        #pragma unroll
        for (int i = 0; i < NC; i++) s += red[i];
        float logz = __logf(s) + logscale + 4254.5374f;   // + 1023*ln(64)
        g_partial[b] = numer - logz;
        __threadfence();
        int v = atomicAdd(&g_done, 1);
        if (v == NB - 1) {                 // last chain: final reduce
            float tot = 0.f;
            #pragma unroll
            for (int i = 0; i < NB; i++) tot += g_partial[i];
            out[out_size - 1] = -tot;
            atomicExch(&g_done, 0);        // reset for graph replay
        }
    }
}

extern "C" void kernel_launch(void* const* d_in, const int* in_sizes, int n_in,
                              void* d_out, int out_size)
{
    const int*   x    = (const int*)  d_in[0];
    const int*   lab  = (const int*)  d_in[1];
    const float* emb  = (const float*)d_in[2];
    const float* fcw  = (const float*)d_in[3];
    const float* fcb  = (const float*)d_in[4];
    const float* st   = (const float*)d_in[5];
    const float* et   = (const float*)d_in[6];
    const float* tr   = (const float*)d_in[7];
    float* out = (float*)d_out;

    cudaFuncSetAttribute(gemm_kernel, cudaFuncAttributeMaxDynamicSharedMemorySize, GEMM_SMEM);
    gemm_kernel<<<NTILES, 256, GEMM_SMEM>>>(x, emb, fcw, fcb, out);
    crf_kernel<<<NB, 64>>>(out, lab, st, et, tr, out, out_size);
}